// round 5
// baseline (speedup 1.0000x reference)
#include <cuda_runtime.h>
#include <math.h>

#define NN 20000
#define NE 40000
#define NG 1000

// Scratch (static __device__ — no allocations allowed)
__device__ float d_h[(size_t)NE * 128];          // edge MLP hidden
__device__ float d_w2t[64 * 8192];               // transposed w2: [i][k*mo+o]
__device__ float d_P[(size_t)NN * 8192];         // per-node precomputed P
__device__ float d_Q[NN * 64];                   // b2 contribution per node
__device__ float d_xa[NN * 64];
__device__ float d_xb[NN * 64];
__device__ float d_agg[NN * 64];
__device__ float d_sums[NG * 64];
__device__ float d_cnt[NG];

__device__ __forceinline__ float eluf(float v) { return v > 0.f ? v : expm1f(v); }

__global__ void zerok(float* __restrict__ p, int n) {
    int i = blockIdx.x * blockDim.x + threadIdx.x;
    if (i < n) p[i] = 0.f;
}

// h[e,j] = relu(b1[j] + sum_a ea[e,a]*w1[a,j]),  j in [0,128)
__global__ void edge_mlp_k(const float* __restrict__ ea, const float* __restrict__ w1,
                           const float* __restrict__ b1, float* __restrict__ h) {
    int e = blockIdx.x, j = threadIdx.x;
    __shared__ float a[5];
    if (j < 5) a[j] = ea[e * 5 + j];
    __syncthreads();
    float s = b1[j];
#pragma unroll
    for (int t = 0; t < 5; t++) s = fmaf(a[t], w1[t * 128 + j], s);
    h[(size_t)e * 128 + j] = fmaxf(s, 0.f);
}

// w2t[i, k*mo+o] = w2[k, i*mo+o]
__global__ void transpose_w2_k(const float* __restrict__ w2, float* __restrict__ w2t,
                               int mi, int mo, int NC, int tot) {
    int idx = blockIdx.x * blockDim.x + threadIdx.x;
    if (idx >= tot) return;
    int k = idx / (mi * mo);
    int r = idx - k * mi * mo;
    int i = r / mo;
    int o = r - i * mo;
    w2t[i * NC + k * mo + o] = w2[idx];
}

// ---------------- GEMM: P[n,c] = sum_i X[n,i]*Wt[i,c] ----------------
// 64x128 tile, 256 threads, 4 rows x 8 cols per thread (32 acc regs).
template<int K>
__global__ void __launch_bounds__(256) gemmP_k(const float* __restrict__ X,
                                               const float* __restrict__ Wt, int NC,
                                               float* __restrict__ P) {
    extern __shared__ float smf[];
    float* Xs = smf;                       // [64][K+1]
    float* Ws = smf + 64 * (K + 1);        // [K][128]
    int c0 = blockIdx.x * 128, n0 = blockIdx.y * 64;
    int tid = threadIdx.x, tx = tid & 15, ty = tid >> 4;

    for (int idx = tid; idx < 64 * K; idx += 256) {
        int r = idx / K, i = idx - r * K;          // coalesced gmem read
        int n = n0 + r;
        Xs[r * (K + 1) + i] = (n < NN) ? X[n * K + i] : 0.f;
    }
    for (int idx = tid; idx < K * 128; idx += 256) {
        int i = idx >> 7, c = idx & 127;
        Ws[i * 128 + c] = Wt[i * NC + c0 + c];
    }
    __syncthreads();

    float acc[4][8] = {};
#pragma unroll 4
    for (int k = 0; k < K; k++) {
        float4 b0 = *(const float4*)(Ws + k * 128 + tx * 8);
        float4 b1 = *(const float4*)(Ws + k * 128 + tx * 8 + 4);
        float a0 = Xs[(ty * 4 + 0) * (K + 1) + k];
        float a1 = Xs[(ty * 4 + 1) * (K + 1) + k];
        float a2 = Xs[(ty * 4 + 2) * (K + 1) + k];
        float a3 = Xs[(ty * 4 + 3) * (K + 1) + k];
        float av[4] = {a0, a1, a2, a3};
#pragma unroll
        for (int r = 0; r < 4; r++) {
            acc[r][0] = fmaf(av[r], b0.x, acc[r][0]);
            acc[r][1] = fmaf(av[r], b0.y, acc[r][1]);
            acc[r][2] = fmaf(av[r], b0.z, acc[r][2]);
            acc[r][3] = fmaf(av[r], b0.w, acc[r][3]);
            acc[r][4] = fmaf(av[r], b1.x, acc[r][4]);
            acc[r][5] = fmaf(av[r], b1.y, acc[r][5]);
            acc[r][6] = fmaf(av[r], b1.z, acc[r][6]);
            acc[r][7] = fmaf(av[r], b1.w, acc[r][7]);
        }
    }
#pragma unroll
    for (int r = 0; r < 4; r++) {
        int n = n0 + ty * 4 + r;
        if (n < NN) {
            float* dst = P + (size_t)n * NC + c0 + tx * 8;
            *(float4*)dst       = make_float4(acc[r][0], acc[r][1], acc[r][2], acc[r][3]);
            *(float4*)(dst + 4) = make_float4(acc[r][4], acc[r][5], acc[r][6], acc[r][7]);
        }
    }
}

// Q[n,o] = sum_i X[n,i] * b2[i*mo+o]
__global__ void qk(const float* __restrict__ X, const float* __restrict__ b2,
                   float* __restrict__ Q, int mi, int mo, int tot) {
    int idx = blockIdx.x * blockDim.x + threadIdx.x;
    if (idx >= tot) return;
    int n = idx / mo, o = idx - n * mo;
    float s = 0.f;
    for (int i = 0; i < mi; i++) s = fmaf(X[n * mi + i], b2[i * mo + o], s);
    Q[idx] = s;
}

// msg[e,o] = Q[src,o] + sum_k h[e,k] * P[src, k*mo+o];  atomic agg[dst,o] +=
__global__ void edge_msg_k(const float* __restrict__ h, const float* __restrict__ P,
                           const float* __restrict__ Q,
                           const int* __restrict__ src, const int* __restrict__ dst,
                           float* __restrict__ agg, int NC, int mo) {
    __shared__ float hs[512];
    int epb = 128 / mo;
    int le = threadIdx.x / mo, o = threadIdx.x - le * mo;
    int e = blockIdx.x * epb + le;
    for (int t = o; t < 128; t += mo) hs[le * 128 + t] = h[(size_t)e * 128 + t];
    __syncthreads();
    int s = src[e], d = dst[e];
    const float* p = P + (size_t)s * NC + o;
    const float* hh = hs + le * 128;
    float acc = Q[s * mo + o];
#pragma unroll 16
    for (int k = 0; k < 128; k++) acc = fmaf(hh[k], p[(size_t)k * mo], acc);
    atomicAdd(&agg[d * mo + o], acc);
}

// Xout[n,o] = elu( sum_i Xin[n,i]*root[i,o] + agg[n,o] + bias[o] )
__global__ void node_update_k(const float* __restrict__ Xin, const float* __restrict__ root,
                              const float* __restrict__ agg, const float* __restrict__ bias,
                              float* __restrict__ Xout, int mi, int mo, int tot) {
    int idx = blockIdx.x * blockDim.x + threadIdx.x;
    if (idx >= tot) return;
    int n = idx / mo, o = idx - n * mo;
    float s = agg[idx] + bias[o];
    for (int i = 0; i < mi; i++) s = fmaf(Xin[n * mi + i], root[i * mo + o], s);
    Xout[idx] = eluf(s);
}

__global__ void pool_k(const float* __restrict__ X, const int* __restrict__ batch,
                       float* __restrict__ sums, float* __restrict__ cnt) {
    int idx = blockIdx.x * blockDim.x + threadIdx.x;
    if (idx >= NN * 64) return;
    int n = idx >> 6, o = idx & 63;
    int g = batch[n];
    atomicAdd(&sums[g * 64 + o], X[idx]);
    if (o == 0) atomicAdd(&cnt[g], 1.f);
}

__global__ void fc_k(const float* __restrict__ sums, const float* __restrict__ cnt,
                     const float* __restrict__ w1, const float* __restrict__ bb1,
                     const float* __restrict__ w2, const float* __restrict__ bb2,
                     const float* __restrict__ w3, const float* __restrict__ bb3,
                     float* __restrict__ out) {
    int g = blockIdx.x, t = threadIdx.x;
    __shared__ float v[64], t1[32], t2[16];
    float c = fmaxf(cnt[g], 1.f);
    v[t] = sums[g * 64 + t] / c;
    __syncthreads();
    if (t < 32) {
        float s = bb1[t];
        for (int i = 0; i < 64; i++) s = fmaf(v[i], w1[i * 32 + t], s);
        t1[t] = eluf(s);
    }
    __syncthreads();
    if (t < 16) {
        float s = bb2[t];
        for (int i = 0; i < 32; i++) s = fmaf(t1[i], w2[i * 16 + t], s);
        t2[t] = eluf(s);
    }
    __syncthreads();
    if (t == 0) {
        float s = bb3[0];
        for (int i = 0; i < 16; i++) s = fmaf(t2[i], w3[i], s);
        out[g] = s;
    }
}

extern "C" void kernel_launch(void* const* d_in, const int* in_sizes, int n_in,
                              void* d_out, int out_size) {
    const float* x     = (const float*)d_in[0];
    const int*   ei    = (const int*)d_in[1];
    const float* ea    = (const float*)d_in[2];
    const int*   batch = (const int*)d_in[3];
    const float *W1[3], *B1[3], *W2[3], *B2[3], *ROOT[3], *BIAS[3];
    for (int l = 0; l < 3; l++) {
        int b = 4 + 6 * l;
        W1[l]   = (const float*)d_in[b + 0];
        B1[l]   = (const float*)d_in[b + 1];
        W2[l]   = (const float*)d_in[b + 2];
        B2[l]   = (const float*)d_in[b + 3];
        ROOT[l] = (const float*)d_in[b + 4];
        BIAS[l] = (const float*)d_in[b + 5];
    }
    const float* fc1w = (const float*)d_in[22];
    const float* fc1b = (const float*)d_in[23];
    const float* fc2w = (const float*)d_in[24];
    const float* fc2b = (const float*)d_in[25];
    const float* fc3w = (const float*)d_in[26];
    const float* fc3b = (const float*)d_in[27];
    float* out = (float*)d_out;

    float *h, *w2t, *P, *Q, *xa, *xb, *agg, *sums, *cnt;
    cudaGetSymbolAddress((void**)&h, d_h);
    cudaGetSymbolAddress((void**)&w2t, d_w2t);
    cudaGetSymbolAddress((void**)&P, d_P);
    cudaGetSymbolAddress((void**)&Q, d_Q);
    cudaGetSymbolAddress((void**)&xa, d_xa);
    cudaGetSymbolAddress((void**)&xb, d_xb);
    cudaGetSymbolAddress((void**)&agg, d_agg);
    cudaGetSymbolAddress((void**)&sums, d_sums);
    cudaGetSymbolAddress((void**)&cnt, d_cnt);

    const int* src = ei;
    const int* dst = ei + NE;

    // GEMM smem sizes (64x128 tile)
    const int SM13 = (64 * 14 + 13 * 128) * 4;   // 10240
    const int SM32 = (64 * 33 + 32 * 128) * 4;   // 24832
    const int SM64 = (64 * 65 + 64 * 128) * 4;   // 49408
    cudaFuncSetAttribute(gemmP_k<13>, cudaFuncAttributeMaxDynamicSharedMemorySize, SM13);
    cudaFuncSetAttribute(gemmP_k<32>, cudaFuncAttributeMaxDynamicSharedMemorySize, SM32);
    cudaFuncSetAttribute(gemmP_k<64>, cudaFuncAttributeMaxDynamicSharedMemorySize, SM64);

    const int MI[3] = {13, 32, 64};
    const int MO[3] = {32, 64, 64};
    const float* xin = x;
    float* xouts[3] = {xa, xb, xa};

    for (int l = 0; l < 3; l++) {
        int mi = MI[l], mo = MO[l], NC = 128 * mo;
        int tq = NN * mo;
        // Order chosen so the profiler's sampled launch (4th) is gemmP<13> on l==0:
        // zerok(1), transpose(2), qk(3), gemmP(4), edge_mlp(5), ...
        zerok<<<(tq + 255) / 256, 256>>>(agg, tq);
        int tot = 128 * mi * mo;
        transpose_w2_k<<<(tot + 255) / 256, 256>>>(W2[l], w2t, mi, mo, NC, tot);
        qk<<<(tq + 255) / 256, 256>>>(xin, B2[l], Q, mi, mo, tq);
        dim3 gp(NC / 128, (NN + 63) / 64);
        if (l == 0)      gemmP_k<13><<<gp, 256, SM13>>>(xin, w2t, NC, P);
        else if (l == 1) gemmP_k<32><<<gp, 256, SM32>>>(xin, w2t, NC, P);
        else             gemmP_k<64><<<gp, 256, SM64>>>(xin, w2t, NC, P);
        edge_mlp_k<<<NE, 128>>>(ea, W1[l], B1[l], h);
        edge_msg_k<<<NE * mo / 128, 128>>>(h, P, Q, src, dst, agg, NC, mo);
        node_update_k<<<(tq + 255) / 256, 256>>>(xin, ROOT[l], agg, BIAS[l], xouts[l], mi, mo, tq);
        xin = xouts[l];
    }
    zerok<<<(NG * 64 + 255) / 256, 256>>>(sums, NG * 64);
    zerok<<<(NG + 255) / 256, 256>>>(cnt, NG);
    pool_k<<<(NN * 64 + 255) / 256, 256>>>(xin, batch, sums, cnt);
    fc_k<<<NG, 64>>>(sums, cnt, fc1w, fc1b, fc2w, fc2b, fc3w, fc3b, out);
}

// round 6
// speedup vs baseline: 1.8309x; 1.8309x over previous
#include <cuda_runtime.h>
#include <cuda_fp16.h>
#include <math.h>

#define NN 20000
#define NE 40000
#define NG 1000

// Scratch (static __device__ — no allocations allowed)
__device__ float d_h[(size_t)NE * 128];          // edge MLP hidden
__device__ float d_w2t[64 * 8192];               // transposed w2: [i][k*mo+o]
__device__ __half d_P[(size_t)NN * 8192];        // per-node precomputed P (fp16)
__device__ float d_Q[NN * 64];                   // b2 contribution per node
__device__ float d_xa[NN * 64];
__device__ float d_xb[NN * 64];
__device__ float d_agg[NN * 64];
__device__ float d_sums[NG * 64];
__device__ float d_cnt[NG];

__device__ __forceinline__ float eluf(float v) { return v > 0.f ? v : expm1f(v); }

__global__ void zerok(float* __restrict__ p, int n) {
    int i = blockIdx.x * blockDim.x + threadIdx.x;
    if (i < n) p[i] = 0.f;
}

// h[e,j] = relu(b1[j] + sum_a ea[e,a]*w1[a,j]),  j in [0,128)
__global__ void edge_mlp_k(const float* __restrict__ ea, const float* __restrict__ w1,
                           const float* __restrict__ b1, float* __restrict__ h) {
    int e = blockIdx.x, j = threadIdx.x;
    __shared__ float a[5];
    if (j < 5) a[j] = ea[e * 5 + j];
    __syncthreads();
    float s = b1[j];
#pragma unroll
    for (int t = 0; t < 5; t++) s = fmaf(a[t], w1[t * 128 + j], s);
    h[(size_t)e * 128 + j] = fmaxf(s, 0.f);
}

// w2t[i, k*mo+o] = w2[k, i*mo+o]
__global__ void transpose_w2_k(const float* __restrict__ w2, float* __restrict__ w2t,
                               int mi, int mo, int NC, int tot) {
    int idx = blockIdx.x * blockDim.x + threadIdx.x;
    if (idx >= tot) return;
    int k = idx / (mi * mo);
    int r = idx - k * mi * mo;
    int i = r / mo;
    int o = r - i * mo;
    w2t[i * NC + k * mo + o] = w2[idx];
}

// P[n, c] = sum_i X[n,i] * Wt[i, c]  — round-1 64x64 tile, 4x4/thread; fp16 store.
__global__ void gemmP_k(const float* __restrict__ X, int K,
                        const float* __restrict__ Wt, int NC,
                        __half* __restrict__ P) {
    __shared__ float Xs[64][65];   // [i][row]
    __shared__ float Ws[64][64];   // [i][col]
    int c0 = blockIdx.x * 64, n0 = blockIdx.y * 64;
    int tid = threadIdx.x;
    int tx = tid & 15, ty = tid >> 4;

    for (int idx = tid; idx < 64 * K; idx += 256) {
        int r = idx / K, i = idx - r * K;      // consecutive tid -> consecutive i (coalesced)
        int n = n0 + r;
        Xs[i][r] = (n < NN) ? X[n * K + i] : 0.f;
    }
    for (int idx = tid; idx < K * 64; idx += 256) {
        int i = idx >> 6, c = idx & 63;
        Ws[i][c] = Wt[i * NC + c0 + c];
    }
    __syncthreads();

    float acc[4][4] = {};
    for (int i = 0; i < K; i++) {
        float4 b = *(const float4*)&Ws[i][tx * 4];
        float a0 = Xs[i][ty * 4 + 0];
        float a1 = Xs[i][ty * 4 + 1];
        float a2 = Xs[i][ty * 4 + 2];
        float a3 = Xs[i][ty * 4 + 3];
        acc[0][0] = fmaf(a0, b.x, acc[0][0]); acc[0][1] = fmaf(a0, b.y, acc[0][1]);
        acc[0][2] = fmaf(a0, b.z, acc[0][2]); acc[0][3] = fmaf(a0, b.w, acc[0][3]);
        acc[1][0] = fmaf(a1, b.x, acc[1][0]); acc[1][1] = fmaf(a1, b.y, acc[1][1]);
        acc[1][2] = fmaf(a1, b.z, acc[1][2]); acc[1][3] = fmaf(a1, b.w, acc[1][3]);
        acc[2][0] = fmaf(a2, b.x, acc[2][0]); acc[2][1] = fmaf(a2, b.y, acc[2][1]);
        acc[2][2] = fmaf(a2, b.z, acc[2][2]); acc[2][3] = fmaf(a2, b.w, acc[2][3]);
        acc[3][0] = fmaf(a3, b.x, acc[3][0]); acc[3][1] = fmaf(a3, b.y, acc[3][1]);
        acc[3][2] = fmaf(a3, b.z, acc[3][2]); acc[3][3] = fmaf(a3, b.w, acc[3][3]);
    }
    for (int r = 0; r < 4; r++) {
        int n = n0 + ty * 4 + r;
        if (n < NN) {
            __half2 h0 = __floats2half2_rn(acc[r][0], acc[r][1]);
            __half2 h1 = __floats2half2_rn(acc[r][2], acc[r][3]);
            __half2* dst = (__half2*)(P + (size_t)n * NC + c0 + tx * 4);
            dst[0] = h0;
            dst[1] = h1;
        }
    }
}

// Q[n,o] = sum_i X[n,i] * b2[i*mo+o]
__global__ void qk(const float* __restrict__ X, const float* __restrict__ b2,
                   float* __restrict__ Q, int mi, int mo, int tot) {
    int idx = blockIdx.x * blockDim.x + threadIdx.x;
    if (idx >= tot) return;
    int n = idx / mo, o = idx - n * mo;
    float s = 0.f;
    for (int i = 0; i < mi; i++) s = fmaf(X[n * mi + i], b2[i * mo + o], s);
    Q[idx] = s;
}

// msg[e,:] = Q[src,:] + sum_k h[e,k] * P[src, k*MO + :]  (P fp16, half2 per thread)
template<int MO>
__global__ void edge_msg_h(const float* __restrict__ h, const __half2* __restrict__ P2,
                           const float* __restrict__ Q,
                           const int* __restrict__ src, const int* __restrict__ dst,
                           float* __restrict__ agg) {
    constexpr int PO = MO / 2;        // half2 lanes per edge
    constexpr int EPB = 128 / PO;     // edges per block
    __shared__ float hs[EPB * 128];
    int le = threadIdx.x / PO, o2 = threadIdx.x - le * PO;
    int e = blockIdx.x * EPB + le;
    for (int t = threadIdx.x; t < EPB * 128; t += 128)
        hs[t] = h[(size_t)blockIdx.x * (EPB * 128) + t];
    __syncthreads();
    int s = src[e], d = dst[e];
    const __half2* p = P2 + (size_t)s * (128 * PO) + o2;   // row = 128*MO halfs
    const float* hh = hs + le * 128;
    float2 q = *(const float2*)&Q[s * MO + 2 * o2];
    float ax0 = q.x, ay0 = q.y, ax1 = 0.f, ay1 = 0.f;
#pragma unroll 8
    for (int k = 0; k < 128; k += 2) {
        float2 p0 = __half22float2(p[(size_t)k * PO]);
        float2 p1 = __half22float2(p[(size_t)(k + 1) * PO]);
        float h0 = hh[k], h1 = hh[k + 1];
        ax0 = fmaf(h0, p0.x, ax0); ay0 = fmaf(h0, p0.y, ay0);
        ax1 = fmaf(h1, p1.x, ax1); ay1 = fmaf(h1, p1.y, ay1);
    }
    atomicAdd(&agg[d * MO + 2 * o2],     ax0 + ax1);
    atomicAdd(&agg[d * MO + 2 * o2 + 1], ay0 + ay1);
}

// Xout[n,o] = elu( sum_i Xin[n,i]*root[i,o] + agg[n,o] + bias[o] )
__global__ void node_update_k(const float* __restrict__ Xin, const float* __restrict__ root,
                              const float* __restrict__ agg, const float* __restrict__ bias,
                              float* __restrict__ Xout, int mi, int mo, int tot) {
    int idx = blockIdx.x * blockDim.x + threadIdx.x;
    if (idx >= tot) return;
    int n = idx / mo, o = idx - n * mo;
    float s = agg[idx] + bias[o];
    for (int i = 0; i < mi; i++) s = fmaf(Xin[n * mi + i], root[i * mo + o], s);
    Xout[idx] = eluf(s);
}

__global__ void pool_k(const float* __restrict__ X, const int* __restrict__ batch,
                       float* __restrict__ sums, float* __restrict__ cnt) {
    int idx = blockIdx.x * blockDim.x + threadIdx.x;
    if (idx >= NN * 64) return;
    int n = idx >> 6, o = idx & 63;
    int g = batch[n];
    atomicAdd(&sums[g * 64 + o], X[idx]);
    if (o == 0) atomicAdd(&cnt[g], 1.f);
}

__global__ void fc_k(const float* __restrict__ sums, const float* __restrict__ cnt,
                     const float* __restrict__ w1, const float* __restrict__ bb1,
                     const float* __restrict__ w2, const float* __restrict__ bb2,
                     const float* __restrict__ w3, const float* __restrict__ bb3,
                     float* __restrict__ out) {
    int g = blockIdx.x, t = threadIdx.x;
    __shared__ float v[64], t1[32], t2[16];
    float c = fmaxf(cnt[g], 1.f);
    v[t] = sums[g * 64 + t] / c;
    __syncthreads();
    if (t < 32) {
        float s = bb1[t];
        for (int i = 0; i < 64; i++) s = fmaf(v[i], w1[i * 32 + t], s);
        t1[t] = eluf(s);
    }
    __syncthreads();
    if (t < 16) {
        float s = bb2[t];
        for (int i = 0; i < 32; i++) s = fmaf(t1[i], w2[i * 16 + t], s);
        t2[t] = eluf(s);
    }
    __syncthreads();
    if (t == 0) {
        float s = bb3[0];
        for (int i = 0; i < 16; i++) s = fmaf(t2[i], w3[i], s);
        out[g] = s;
    }
}

extern "C" void kernel_launch(void* const* d_in, const int* in_sizes, int n_in,
                              void* d_out, int out_size) {
    const float* x     = (const float*)d_in[0];
    const int*   ei    = (const int*)d_in[1];
    const float* ea    = (const float*)d_in[2];
    const int*   batch = (const int*)d_in[3];
    const float *W1[3], *B1[3], *W2[3], *B2[3], *ROOT[3], *BIAS[3];
    for (int l = 0; l < 3; l++) {
        int b = 4 + 6 * l;
        W1[l]   = (const float*)d_in[b + 0];
        B1[l]   = (const float*)d_in[b + 1];
        W2[l]   = (const float*)d_in[b + 2];
        B2[l]   = (const float*)d_in[b + 3];
        ROOT[l] = (const float*)d_in[b + 4];
        BIAS[l] = (const float*)d_in[b + 5];
    }
    const float* fc1w = (const float*)d_in[22];
    const float* fc1b = (const float*)d_in[23];
    const float* fc2w = (const float*)d_in[24];
    const float* fc2b = (const float*)d_in[25];
    const float* fc3w = (const float*)d_in[26];
    const float* fc3b = (const float*)d_in[27];
    float* out = (float*)d_out;

    float *h, *w2t, *Q, *xa, *xb, *agg, *sums, *cnt;
    __half* P;
    cudaGetSymbolAddress((void**)&h, d_h);
    cudaGetSymbolAddress((void**)&w2t, d_w2t);
    cudaGetSymbolAddress((void**)&P, d_P);
    cudaGetSymbolAddress((void**)&Q, d_Q);
    cudaGetSymbolAddress((void**)&xa, d_xa);
    cudaGetSymbolAddress((void**)&xb, d_xb);
    cudaGetSymbolAddress((void**)&agg, d_agg);
    cudaGetSymbolAddress((void**)&sums, d_sums);
    cudaGetSymbolAddress((void**)&cnt, d_cnt);

    const int* src = ei;
    const int* dst = ei + NE;
    const int MI[3] = {13, 32, 64};
    const int MO[3] = {32, 64, 64};
    const float* xin = x;
    float* xouts[3] = {xa, xb, xa};

    for (int l = 0; l < 3; l++) {
        int mi = MI[l], mo = MO[l], NC = 128 * mo;
        int tq = NN * mo;
        // Launch order keeps the profiler's sampled slot (#4) on gemmP (layer 0).
        zerok<<<(tq + 255) / 256, 256>>>(agg, tq);
        int tot = 128 * mi * mo;
        transpose_w2_k<<<(tot + 255) / 256, 256>>>(W2[l], w2t, mi, mo, NC, tot);
        qk<<<(tq + 255) / 256, 256>>>(xin, B2[l], Q, mi, mo, tq);
        dim3 gp(NC / 64, (NN + 63) / 64);
        gemmP_k<<<gp, 256>>>(xin, mi, w2t, NC, P);
        edge_mlp_k<<<NE, 128>>>(ea, W1[l], B1[l], h);
        if (l == 0) edge_msg_h<32><<<NE / 8, 128>>>(h, (const __half2*)P, Q, src, dst, agg);
        else        edge_msg_h<64><<<NE / 4, 128>>>(h, (const __half2*)P, Q, src, dst, agg);
        node_update_k<<<(tq + 255) / 256, 256>>>(xin, ROOT[l], agg, BIAS[l], xouts[l], mi, mo, tq);
        xin = xouts[l];
    }
    zerok<<<(NG * 64 + 255) / 256, 256>>>(sums, NG * 64);
    zerok<<<(NG + 255) / 256, 256>>>(cnt, NG);
    pool_k<<<(NN * 64 + 255) / 256, 256>>>(xin, batch, sums, cnt);
    fc_k<<<NG, 64>>>(sums, cnt, fc1w, fc1b, fc2w, fc2b, fc3w, fc3b, out);
}

// round 8
// speedup vs baseline: 1.9795x; 1.0812x over previous
#include <cuda_runtime.h>
#include <cuda_fp16.h>
#include <math.h>

#define NN 20000
#define NE 40000
#define NG 1000

// Scratch (static __device__ — no allocations allowed)
__device__ float d_h[(size_t)NE * 128];          // edge MLP hidden
__device__ float d_w2t[64 * 8192];               // transposed w2: [i][k*mo+o]
__device__ __half d_P[(size_t)NN * 8192];        // per-node precomputed P (fp16)
__device__ float d_Q[NN * 64];                   // b2 contribution per node
__device__ float d_xa[NN * 64];
__device__ float d_xb[NN * 64];
__device__ float d_agg[NN * 64];
__device__ float d_sums[NG * 64];
__device__ float d_cnt[NG];

__device__ __forceinline__ float eluf(float v) { return v > 0.f ? v : expm1f(v); }

__global__ void zerok(float* __restrict__ p, int n) {
    int i = blockIdx.x * blockDim.x + threadIdx.x;
    if (i < n) p[i] = 0.f;
}

// h[e,j] = relu(b1[j] + sum_a ea[e,a]*w1[a,j]),  j in [0,128)
__global__ void edge_mlp_k(const float* __restrict__ ea, const float* __restrict__ w1,
                           const float* __restrict__ b1, float* __restrict__ h) {
    int e = blockIdx.x, j = threadIdx.x;
    __shared__ float a[5];
    if (j < 5) a[j] = ea[e * 5 + j];
    __syncthreads();
    float s = b1[j];
#pragma unroll
    for (int t = 0; t < 5; t++) s = fmaf(a[t], w1[t * 128 + j], s);
    h[(size_t)e * 128 + j] = fmaxf(s, 0.f);
}

// w2t[i, k*mo+o] = w2[k, i*mo+o]
__global__ void transpose_w2_k(const float* __restrict__ w2, float* __restrict__ w2t,
                               int mi, int mo, int NC, int tot) {
    int idx = blockIdx.x * blockDim.x + threadIdx.x;
    if (idx >= tot) return;
    int k = idx / (mi * mo);
    int r = idx - k * mi * mo;
    int i = r / mo;
    int o = r - i * mo;
    w2t[i * NC + k * mo + o] = w2[idx];
}

// P[n, c] = sum_i X[n,i] * Wt[i, c] — 64x64 tile, 4x4/thread, fp16 store.
// K compile-time: main loop fully unrolled. Ws declared FIRST and 16B-aligned
// (float4 loads); Xs scalar-accessed only, so its placement is alignment-safe.
template<int K>
__global__ void __launch_bounds__(256) gemmP_k(const float* __restrict__ X,
                                               const float* __restrict__ Wt, int NC,
                                               __half* __restrict__ P) {
    __shared__ __align__(16) float Ws[K][64];   // [i][col] — float4 reads
    __shared__ float Xs[K][65];                 // [i][row] — scalar reads
    int c0 = blockIdx.x * 64, n0 = blockIdx.y * 64;
    int tid = threadIdx.x;
    int tx = tid & 15, ty = tid >> 4;

#pragma unroll 1
    for (int idx = tid; idx < 64 * K; idx += 256) {
        int r = idx / K, i = idx - r * K;      // K constant -> mul-shift
        int n = n0 + r;
        Xs[i][r] = (n < NN) ? X[n * K + i] : 0.f;
    }
#pragma unroll 1
    for (int idx = tid; idx < K * 64; idx += 256) {
        int i = idx >> 6, c = idx & 63;
        Ws[i][c] = Wt[i * NC + c0 + c];
    }
    __syncthreads();

    float acc[4][4] = {};
#pragma unroll
    for (int i = 0; i < K; i++) {
        float4 b = *(const float4*)&Ws[i][tx * 4];
        float a0 = Xs[i][ty * 4 + 0];
        float a1 = Xs[i][ty * 4 + 1];
        float a2 = Xs[i][ty * 4 + 2];
        float a3 = Xs[i][ty * 4 + 3];
        acc[0][0] = fmaf(a0, b.x, acc[0][0]); acc[0][1] = fmaf(a0, b.y, acc[0][1]);
        acc[0][2] = fmaf(a0, b.z, acc[0][2]); acc[0][3] = fmaf(a0, b.w, acc[0][3]);
        acc[1][0] = fmaf(a1, b.x, acc[1][0]); acc[1][1] = fmaf(a1, b.y, acc[1][1]);
        acc[1][2] = fmaf(a1, b.z, acc[1][2]); acc[1][3] = fmaf(a1, b.w, acc[1][3]);
        acc[2][0] = fmaf(a2, b.x, acc[2][0]); acc[2][1] = fmaf(a2, b.y, acc[2][1]);
        acc[2][2] = fmaf(a2, b.z, acc[2][2]); acc[2][3] = fmaf(a2, b.w, acc[2][3]);
        acc[3][0] = fmaf(a3, b.x, acc[3][0]); acc[3][1] = fmaf(a3, b.y, acc[3][1]);
        acc[3][2] = fmaf(a3, b.z, acc[3][2]); acc[3][3] = fmaf(a3, b.w, acc[3][3]);
    }
#pragma unroll
    for (int r = 0; r < 4; r++) {
        int n = n0 + ty * 4 + r;
        if (n < NN) {
            __half2 h0 = __floats2half2_rn(acc[r][0], acc[r][1]);
            __half2 h1 = __floats2half2_rn(acc[r][2], acc[r][3]);
            __half2* dst = (__half2*)(P + (size_t)n * NC + c0 + tx * 4);
            dst[0] = h0;
            dst[1] = h1;
        }
    }
}

// Q[n,o] = sum_i X[n,i] * b2[i*mo+o]
__global__ void qk(const float* __restrict__ X, const float* __restrict__ b2,
                   float* __restrict__ Q, int mi, int mo, int tot) {
    int idx = blockIdx.x * blockDim.x + threadIdx.x;
    if (idx >= tot) return;
    int n = idx / mo, o = idx - n * mo;
    float s = 0.f;
    for (int i = 0; i < mi; i++) s = fmaf(X[n * mi + i], b2[i * mo + o], s);
    Q[idx] = s;
}

// msg[e,:] = Q[src,:] + sum_k h[e,k] * P[src, k*MO + :]  (P fp16, half2 per thread)
template<int MO>
__global__ void edge_msg_h(const float* __restrict__ h, const __half2* __restrict__ P2,
                           const float* __restrict__ Q,
                           const int* __restrict__ src, const int* __restrict__ dst,
                           float* __restrict__ agg) {
    constexpr int PO = MO / 2;        // half2 lanes per edge
    constexpr int EPB = 128 / PO;     // edges per block
    __shared__ float hs[EPB * 128];
    int le = threadIdx.x / PO, o2 = threadIdx.x - le * PO;
    int e = blockIdx.x * EPB + le;
    for (int t = threadIdx.x; t < EPB * 128; t += 128)
        hs[t] = h[(size_t)blockIdx.x * (EPB * 128) + t];
    __syncthreads();
    int s = src[e], d = dst[e];
    const __half2* p = P2 + (size_t)s * (128 * PO) + o2;   // row = 128*MO halfs
    const float* hh = hs + le * 128;
    float2 q = *(const float2*)&Q[s * MO + 2 * o2];
    float ax0 = q.x, ay0 = q.y, ax1 = 0.f, ay1 = 0.f;
#pragma unroll 8
    for (int k = 0; k < 128; k += 2) {
        float2 p0 = __half22float2(p[(size_t)k * PO]);
        float2 p1 = __half22float2(p[(size_t)(k + 1) * PO]);
        float h0 = hh[k], h1 = hh[k + 1];
        ax0 = fmaf(h0, p0.x, ax0); ay0 = fmaf(h0, p0.y, ay0);
        ax1 = fmaf(h1, p1.x, ax1); ay1 = fmaf(h1, p1.y, ay1);
    }
    atomicAdd(&agg[d * MO + 2 * o2],     ax0 + ax1);
    atomicAdd(&agg[d * MO + 2 * o2 + 1], ay0 + ay1);
}

// Xout[n,o] = elu( sum_i Xin[n,i]*root[i,o] + agg[n,o] + bias[o] )
__global__ void node_update_k(const float* __restrict__ Xin, const float* __restrict__ root,
                              const float* __restrict__ agg, const float* __restrict__ bias,
                              float* __restrict__ Xout, int mi, int mo, int tot) {
    int idx = blockIdx.x * blockDim.x + threadIdx.x;
    if (idx >= tot) return;
    int n = idx / mo, o = idx - n * mo;
    float s = agg[idx] + bias[o];
    for (int i = 0; i < mi; i++) s = fmaf(Xin[n * mi + i], root[i * mo + o], s);
    Xout[idx] = eluf(s);
}

__global__ void pool_k(const float* __restrict__ X, const int* __restrict__ batch,
                       float* __restrict__ sums, float* __restrict__ cnt) {
    int idx = blockIdx.x * blockDim.x + threadIdx.x;
    if (idx >= NN * 64) return;
    int n = idx >> 6, o = idx & 63;
    int g = batch[n];
    atomicAdd(&sums[g * 64 + o], X[idx]);
    if (o == 0) atomicAdd(&cnt[g], 1.f);
}

__global__ void fc_k(const float* __restrict__ sums, const float* __restrict__ cnt,
                     const float* __restrict__ w1, const float* __restrict__ bb1,
                     const float* __restrict__ w2, const float* __restrict__ bb2,
                     const float* __restrict__ w3, const float* __restrict__ bb3,
                     float* __restrict__ out) {
    int g = blockIdx.x, t = threadIdx.x;
    __shared__ float v[64], t1[32], t2[16];
    float c = fmaxf(cnt[g], 1.f);
    v[t] = sums[g * 64 + t] / c;
    __syncthreads();
    if (t < 32) {
        float s = bb1[t];
        for (int i = 0; i < 64; i++) s = fmaf(v[i], w1[i * 32 + t], s);
        t1[t] = eluf(s);
    }
    __syncthreads();
    if (t < 16) {
        float s = bb2[t];
        for (int i = 0; i < 32; i++) s = fmaf(t1[i], w2[i * 16 + t], s);
        t2[t] = eluf(s);
    }
    __syncthreads();
    if (t == 0) {
        float s = bb3[0];
        for (int i = 0; i < 16; i++) s = fmaf(t2[i], w3[i], s);
        out[g] = s;
    }
}

extern "C" void kernel_launch(void* const* d_in, const int* in_sizes, int n_in,
                              void* d_out, int out_size) {
    const float* x     = (const float*)d_in[0];
    const int*   ei    = (const int*)d_in[1];
    const float* ea    = (const float*)d_in[2];
    const int*   batch = (const int*)d_in[3];
    const float *W1[3], *B1[3], *W2[3], *B2[3], *ROOT[3], *BIAS[3];
    for (int l = 0; l < 3; l++) {
        int b = 4 + 6 * l;
        W1[l]   = (const float*)d_in[b + 0];
        B1[l]   = (const float*)d_in[b + 1];
        W2[l]   = (const float*)d_in[b + 2];
        B2[l]   = (const float*)d_in[b + 3];
        ROOT[l] = (const float*)d_in[b + 4];
        BIAS[l] = (const float*)d_in[b + 5];
    }
    const float* fc1w = (const float*)d_in[22];
    const float* fc1b = (const float*)d_in[23];
    const float* fc2w = (const float*)d_in[24];
    const float* fc2b = (const float*)d_in[25];
    const float* fc3w = (const float*)d_in[26];
    const float* fc3b = (const float*)d_in[27];
    float* out = (float*)d_out;

    float *h, *w2t, *Q, *xa, *xb, *agg, *sums, *cnt;
    __half* P;
    cudaGetSymbolAddress((void**)&h, d_h);
    cudaGetSymbolAddress((void**)&w2t, d_w2t);
    cudaGetSymbolAddress((void**)&P, d_P);
    cudaGetSymbolAddress((void**)&Q, d_Q);
    cudaGetSymbolAddress((void**)&xa, d_xa);
    cudaGetSymbolAddress((void**)&xb, d_xb);
    cudaGetSymbolAddress((void**)&agg, d_agg);
    cudaGetSymbolAddress((void**)&sums, d_sums);
    cudaGetSymbolAddress((void**)&cnt, d_cnt);

    const int* src = ei;
    const int* dst = ei + NE;
    const int MI[3] = {13, 32, 64};
    const int MO[3] = {32, 64, 64};
    const float* xin = x;
    float* xouts[3] = {xa, xb, xa};

    for (int l = 0; l < 3; l++) {
        int mi = MI[l], mo = MO[l], NC = 128 * mo;
        int tq = NN * mo;
        // Launch order keeps the profiler's sampled slot (#4) on gemmP (layer 0).
        zerok<<<(tq + 255) / 256, 256>>>(agg, tq);
        int tot = 128 * mi * mo;
        transpose_w2_k<<<(tot + 255) / 256, 256>>>(W2[l], w2t, mi, mo, NC, tot);
        qk<<<(tq + 255) / 256, 256>>>(xin, B2[l], Q, mi, mo, tq);
        dim3 gp(NC / 64, (NN + 63) / 64);
        if (l == 0)      gemmP_k<13><<<gp, 256>>>(xin, w2t, NC, P);
        else if (l == 1) gemmP_k<32><<<gp, 256>>>(xin, w2t, NC, P);
        else             gemmP_k<64><<<gp, 256>>>(xin, w2t, NC, P);
        edge_mlp_k<<<NE, 128>>>(ea, W1[l], B1[l], h);
        if (l == 0) edge_msg_h<32><<<NE / 8, 128>>>(h, (const __half2*)P, Q, src, dst, agg);
        else        edge_msg_h<64><<<NE / 4, 128>>>(h, (const __half2*)P, Q, src, dst, agg);
        node_update_k<<<(tq + 255) / 256, 256>>>(xin, ROOT[l], agg, BIAS[l], xouts[l], mi, mo, tq);
        xin = xouts[l];
    }
    zerok<<<(NG * 64 + 255) / 256, 256>>>(sums, NG * 64);
    zerok<<<(NG + 255) / 256, 256>>>(cnt, NG);
    pool_k<<<(NN * 64 + 255) / 256, 256>>>(xin, batch, sums, cnt);
    fc_k<<<NG, 64>>>(sums, cnt, fc1w, fc1b, fc2w, fc2b, fc3w, fc3b, out);
}